// round 12
// baseline (speedup 1.0000x reference)
#include <cuda_runtime.h>
#include <cuda_bf16.h>
#include <cstdint>

#define INPUT_DIM 16384
#define EMB 1024
#define BATCH 4096
#define XS_N (INPUT_DIM + EMB * 3)   // 19456 floats, pad-4 bound (<32768, fits 15 bits)

#define GTHREADS 512
#define GRID_G   296                 // 2 CTAs/SM x 148 SMs -> all resident, spin barriers safe
#define NWARPS_G (GRID_G * GTHREADS / 32)   // 4736

// ---------------- device scratch ----------------
__device__ unsigned short g_comb[INPUT_DIM];                 // e | (neg<<15) per feature j
__device__ __align__(16) unsigned short g_pos[INPUT_DIM];    // slot | (neg<<15), by j
__device__ int g_astart[EMB];                                // pad-4 bucket start
__device__ int g_len[EMB];                                   // actual bucket length
__device__ int g_b1;                                         // grid barrier counters (BSS=0)
__device__ int g_b2;

__global__ __launch_bounds__(GTHREADS, 2)
void k_all(const float* __restrict__ x, const float* __restrict__ hp,
           float* __restrict__ out) {
    extern __shared__ float xs[];          // [XS_N]; CTA0 aliases build scratch here first
    __shared__ int wsum[16];
    int t = threadIdx.x;
    int lane = t & 31;
    int cta  = blockIdx.x;

    // replay-safe: g_b2 must be 0 before any CTA can arrive at barrier 2.
    // Any b2 arrival requires barrier 1 completion, which requires CTA0's b1
    // arrival, which happens after this reset. g_b1 is reset at the end (below).
    if (cta == 0 && t == 0) g_b2 = 0;

    // ---------------- Phase 1: extract (warp per hashProj row, strided) ----------------
    {
        int gw = (cta * GTHREADS + t) >> 5;          // 0..4735
        for (int row_j = gw; row_j < INPUT_DIM; row_j += NWARPS_G) {
            const float4* row = reinterpret_cast<const float4*>(hp + (size_t)row_j * EMB);
            float4 c[4];
            int my_e = 0; unsigned my_neg = 0; bool has = false;
#pragma unroll
            for (int i = 0; i < 4; i++) c[i] = row[lane + i * 32];
#pragma unroll
            for (int i = 0; i < 4; i++) {
                int base = (lane + i * 32) * 4;
                if (c[i].x != 0.0f) { my_e = base + 0; my_neg = (c[i].x < 0.0f); has = true; }
                if (c[i].y != 0.0f) { my_e = base + 1; my_neg = (c[i].y < 0.0f); has = true; }
                if (c[i].z != 0.0f) { my_e = base + 2; my_neg = (c[i].z < 0.0f); has = true; }
                if (c[i].w != 0.0f) { my_e = base + 3; my_neg = (c[i].w < 0.0f); has = true; }
            }
            unsigned mask = __ballot_sync(0xffffffffu, has);
            if (mask == 0) {
#pragma unroll
                for (int i = 0; i < 4; i++) c[i] = row[lane + (i + 4) * 32];
#pragma unroll
                for (int i = 0; i < 4; i++) {
                    int base = (lane + (i + 4) * 32) * 4;
                    if (c[i].x != 0.0f) { my_e = base + 0; my_neg = (c[i].x < 0.0f); has = true; }
                    if (c[i].y != 0.0f) { my_e = base + 1; my_neg = (c[i].y < 0.0f); has = true; }
                    if (c[i].z != 0.0f) { my_e = base + 2; my_neg = (c[i].z < 0.0f); has = true; }
                    if (c[i].w != 0.0f) { my_e = base + 3; my_neg = (c[i].w < 0.0f); has = true; }
                }
                mask = __ballot_sync(0xffffffffu, has);
            }
            if (mask == 0) { if (lane == 0) g_comb[row_j] = 0; continue; }
            int src = __ffs(mask) - 1;
            int e        = __shfl_sync(0xffffffffu, my_e, src);
            unsigned neg = __shfl_sync(0xffffffffu, my_neg, src);
            if (lane == 0) g_comb[row_j] = (unsigned short)(e | (neg << 15));
        }
    }

    // ---------------- grid barrier 1 ----------------
    __syncthreads();
    if (t == 0) { __threadfence(); atomicAdd(&g_b1, 1); }
    if (t == 0) { while (*(volatile int*)&g_b1 < GRID_G) { } __threadfence(); }
    __syncthreads();

    float4 v[8];                           // first-row prefetch target
    int b = cta;

    if (cta == 0) {
        // ---------------- Phase 2: build (CTA 0 only; smem scratch aliased in xs) ----------------
        int* hist = reinterpret_cast<int*>(xs);        // [EMB]
        int* cur  = hist + EMB;                        // [EMB]
        hist[t] = 0; hist[t + GTHREADS] = 0;
        __syncthreads();
#pragma unroll
        for (int i = 0; i < INPUT_DIM / GTHREADS; i++)
            atomicAdd(&hist[g_comb[i * GTHREADS + t] & (EMB - 1)], 1);
        __syncthreads();

        int c0 = hist[t], c1 = hist[t + GTHREADS];
        int p0 = (c0 + 3) & ~3, p1 = (c1 + 3) & ~3;
        int pair = p0 + p1;

        // inclusive scan of pair over 512 threads
        int w = t >> 5;
        int s = pair;
#pragma unroll
        for (int off = 1; off < 32; off <<= 1) {
            int n = __shfl_up_sync(0xffffffffu, s, off);
            if (lane >= off) s += n;
        }
        if (lane == 31) wsum[w] = s;
        __syncthreads();
        if (w == 0 && lane < 16) {
            int sv = wsum[lane];
#pragma unroll
            for (int off = 1; off < 16; off <<= 1) {
                int n = __shfl_up_sync(0xffffu, sv, off);
                if (lane >= off) sv += n;
            }
            wsum[lane] = sv;
        }
        __syncthreads();
        int excl = s - pair + (w > 0 ? wsum[w - 1] : 0);
        g_astart[t] = excl;            g_len[t] = c0;            cur[t] = excl;
        g_astart[t + GTHREADS] = excl + p0; g_len[t + GTHREADS] = c1; cur[t + GTHREADS] = excl + p0;
        __syncthreads();

#pragma unroll
        for (int i = 0; i < INPUT_DIM / GTHREADS; i++) {
            int j = i * GTHREADS + t;
            unsigned cb = g_comb[j];
            int pos = atomicAdd(&cur[cb & (EMB - 1)], 1);
            g_pos[j] = (unsigned short)(pos | (cb & 0x8000u));
        }
        __syncthreads();

        // prefetch first row, then release
        {
            const float4* gx = reinterpret_cast<const float4*>(x + (size_t)b * INPUT_DIM);
#pragma unroll
            for (int i = 0; i < 8; i++) v[i] = gx[t + i * GTHREADS];
        }
        if (t == 0) { __threadfence(); atomicAdd(&g_b2, 1); }
    } else {
        // other CTAs: stream first x row NOW (overlaps CTA0's build), then arrive
        {
            const float4* gx = reinterpret_cast<const float4*>(x + (size_t)b * INPUT_DIM);
#pragma unroll
            for (int i = 0; i < 8; i++) v[i] = gx[t + i * GTHREADS];
        }
        if (t == 0) atomicAdd(&g_b2, 1);
    }

    // ---------------- grid barrier 2 ----------------
    if (t == 0) { while (*(volatile int*)&g_b2 < GRID_G) { } __threadfence(); }
    __syncthreads();
    if (cta == 0 && t == 0) g_b1 = 0;      // replay-safe reset (all CTAs passed b1)

    // ---------------- Phase 3: persistent pipelined gather (R11 form) ----------------
    int s0a = __ldg(&g_astart[t]);
    int la  = __ldg(&g_len[t]);
    int s0b = __ldg(&g_astart[t + GTHREADS]);
    int lb  = __ldg(&g_len[t + GTHREADS]);

    uint2 q[8];
    {
        const uint2* gp = reinterpret_cast<const uint2*>(g_pos);
#pragma unroll
        for (int i = 0; i < 8; i++) q[i] = gp[t + i * GTHREADS];
    }

    // zero pad slots once (scatter never writes pads)
    {
        int pa = (la + 3) & ~3;
        for (int k = s0a + la; k < s0a + pa; k++) xs[k] = 0.0f;
        int pb = (lb + 3) & ~3;
        for (int k = s0b + lb; k < s0b + pb; k++) xs[k] = 0.0f;
    }

    int n4a = ((la + 3) & ~3) >> 2;
    int n4b = ((lb + 3) & ~3) >> 2;

    for (; b < BATCH; b += GRID_G) {
        __syncthreads();                   // pads ready / previous Phase C done reading xs

        // scatter current row from registers (sign-applied)
#pragma unroll
        for (int i = 0; i < 8; i++) {
            unsigned q0 = q[i].x & 0xFFFFu, q1 = q[i].x >> 16;
            unsigned q2 = q[i].y & 0xFFFFu, q3 = q[i].y >> 16;
            xs[q0 & 0x7FFFu] = __uint_as_float(__float_as_uint(v[i].x) ^ ((q0 & 0x8000u) << 16));
            xs[q1 & 0x7FFFu] = __uint_as_float(__float_as_uint(v[i].y) ^ ((q1 & 0x8000u) << 16));
            xs[q2 & 0x7FFFu] = __uint_as_float(__float_as_uint(v[i].z) ^ ((q2 & 0x8000u) << 16));
            xs[q3 & 0x7FFFu] = __uint_as_float(__float_as_uint(v[i].w) ^ ((q3 & 0x8000u) << 16));
        }

        // issue next row's loads — DRAM streams during barrier + Phase C
        int bn = b + GRID_G;
        if (bn < BATCH) {
            const float4* gx = reinterpret_cast<const float4*>(x + (size_t)bn * INPUT_DIM);
#pragma unroll
            for (int i = 0; i < 8; i++) v[i] = gx[t + i * GTHREADS];
        }

        __syncthreads();                   // scatter visible

        float* o = out + (size_t)b * EMB;
        {
            const float4* xs4 = reinterpret_cast<const float4*>(xs) + (s0a >> 2);
            float acc = 0.0f;
            for (int i = 0; i < n4a; i++) {
                float4 u = xs4[i];
                acc += (u.x + u.y) + (u.z + u.w);
            }
            o[t] = acc;
        }
        {
            const float4* xs4 = reinterpret_cast<const float4*>(xs) + (s0b >> 2);
            float acc = 0.0f;
            for (int i = 0; i < n4b; i++) {
                float4 u = xs4[i];
                acc += (u.x + u.y) + (u.z + u.w);
            }
            o[t + GTHREADS] = acc;
        }
    }
}

extern "C" void kernel_launch(void* const* d_in, const int* in_sizes, int n_in,
                              void* d_out, int out_size) {
    const float* x  = (const float*)d_in[0];   // [BATCH, INPUT_DIM]
    const float* hp = (const float*)d_in[1];   // [INPUT_DIM, EMB]
    float* out = (float*)d_out;                // [BATCH, EMB]

    int smem = XS_N * (int)sizeof(float);      // 77824 B -> 2 blocks/SM
    cudaFuncSetAttribute(k_all, cudaFuncAttributeMaxDynamicSharedMemorySize, smem);

    k_all<<<GRID_G, GTHREADS, smem>>>(x, hp, out);
}